// round 3
// baseline (speedup 1.0000x reference)
#include <cuda_runtime.h>
#include <math.h>

#define NN 16384
#define GG 128
#define E0C 262144
#define KK 8

typedef unsigned long long ull;

// ---------------- scratch (device globals; no allocations allowed) ----------
__device__ float g_h1[NN * 16];
__device__ float g_h2[NN * 8];
__device__ int   g_knn[NN * KK];
__device__ float g_h3[NN * 8];
__device__ float g_h4[NN * 16];

// ---------------- packed f32x2 helpers (Blackwell FFMA2) ---------------------
__device__ __forceinline__ ull pack2(float lo, float hi) {
    ull r; asm("mov.b64 %0, {%1, %2};" : "=l"(r) : "f"(lo), "f"(hi)); return r;
}
__device__ __forceinline__ void unpack2(float& lo, float& hi, ull v) {
    asm("mov.b64 {%0, %1}, %2;" : "=f"(lo), "=f"(hi) : "l"(v));
}
__device__ __forceinline__ ull ffma2(ull a, ull b, ull c) {
    ull d; asm("fma.rn.f32x2 %0, %1, %2, %3;" : "=l"(d) : "l"(a), "l"(b), "l"(c));
    return d;
}

// ---------------- init: zero atomic-max accumulators ------------------------
__global__ void k_init() {
    int i = blockIdx.x * blockDim.x + threadIdx.x;
    if (i < NN * 16) g_h1[i] = 0.0f;
    if (i < NN * 8)  g_h2[i] = 0.0f;
}

// ---------------- conv1: x[N,3] -> h1[N,16] (6->16 relu ->16) ---------------
__global__ void k_conv1(const float* __restrict__ x, const int* __restrict__ ei,
                        const float* __restrict__ w1, const float* __restrict__ b1,
                        const float* __restrict__ w2, const float* __restrict__ b2) {
    __shared__ float sw1[96], sb1[16], sw2[256], sb2[16];
    int t = threadIdx.x;
    for (int v = t; v < 96;  v += blockDim.x) sw1[v] = w1[v];
    for (int v = t; v < 256; v += blockDim.x) sw2[v] = w2[v];
    if (t < 16) { sb1[t] = b1[t]; sb2[t] = b2[t]; }
    __syncthreads();
    int e = blockIdx.x * blockDim.x + t;
    if (e >= E0C) return;
    int s = ei[e], d = ei[E0C + e];
    float xi0 = x[d * 3], xi1 = x[d * 3 + 1], xi2 = x[d * 3 + 2];
    float m[6] = { xi0, xi1, xi2,
                   x[s * 3] - xi0, x[s * 3 + 1] - xi1, x[s * 3 + 2] - xi2 };
    float h[16];
#pragma unroll
    for (int o = 0; o < 16; ++o) h[o] = sb1[o];
#pragma unroll
    for (int i = 0; i < 6; ++i) {
        float mv = m[i];
#pragma unroll
        for (int o = 0; o < 16; ++o) h[o] += mv * sw1[i * 16 + o];
    }
#pragma unroll
    for (int o = 0; o < 16; ++o) h[o] = fmaxf(h[o], 0.0f);
    int* dst = (int*)&g_h1[d * 16];
#pragma unroll
    for (int o = 0; o < 16; ++o) {
        float v = sb2[o];
#pragma unroll
        for (int i = 0; i < 16; ++i) v += h[i] * sw2[i * 16 + o];
        atomicMax(dst + o, __float_as_int(fmaxf(v, 0.0f)));
    }
}

// ---------------- conv2: h1[N,16] -> h2[N,8] (32->8 relu ->8) ---------------
__global__ void k_conv2(const int* __restrict__ ei,
                        const float* __restrict__ w1, const float* __restrict__ b1,
                        const float* __restrict__ w2, const float* __restrict__ b2) {
    __shared__ float sw1[256], sb1[8], sw2[64], sb2[8];
    int t = threadIdx.x;
    for (int v = t; v < 256; v += blockDim.x) sw1[v] = w1[v];
    for (int v = t; v < 64;  v += blockDim.x) sw2[v] = w2[v];
    if (t < 8) { sb1[t] = b1[t]; sb2[t] = b2[t]; }
    __syncthreads();
    int e = blockIdx.x * blockDim.x + t;
    if (e >= E0C) return;
    int s = ei[e], d = ei[E0C + e];
    const float4* Xi = (const float4*)&g_h1[d * 16];
    const float4* Xj = (const float4*)&g_h1[s * 16];
    float xi[16], xj[16];
#pragma unroll
    for (int q = 0; q < 4; ++q) {
        float4 a = Xi[q], b = Xj[q];
        xi[q * 4 + 0] = a.x; xi[q * 4 + 1] = a.y; xi[q * 4 + 2] = a.z; xi[q * 4 + 3] = a.w;
        xj[q * 4 + 0] = b.x; xj[q * 4 + 1] = b.y; xj[q * 4 + 2] = b.z; xj[q * 4 + 3] = b.w;
    }
    float h[8];
#pragma unroll
    for (int o = 0; o < 8; ++o) h[o] = sb1[o];
#pragma unroll
    for (int f = 0; f < 16; ++f) {
        float m0 = xi[f], m1 = xj[f] - xi[f];
#pragma unroll
        for (int o = 0; o < 8; ++o)
            h[o] += m0 * sw1[f * 8 + o] + m1 * sw1[(16 + f) * 8 + o];
    }
#pragma unroll
    for (int o = 0; o < 8; ++o) h[o] = fmaxf(h[o], 0.0f);
    int* dst = (int*)&g_h2[d * 8];
#pragma unroll
    for (int o = 0; o < 8; ++o) {
        float v = sb2[o];
#pragma unroll
        for (int i = 0; i < 8; ++i) v += h[i] * sw2[i * 8 + o];
        atomicMax(dst + o, __float_as_int(fmaxf(v, 0.0f)));
    }
}

// ---------------- kNN -------------------------------------------------------
// Rank by score s = dot(q,p) - 0.5*|p|^2 (monotone in -distance; sq_i cancels).
// 512 blocks x 128 threads. Block owns 32 queries (8 groups x QT=4).
// Thread (slice s in 0..15, group qg in 0..7) scans 1/16 of the points for its
// 4 queries: one 40B shared point load feeds 4 independent FFMA2 chains
// (LDS/dist = 10B, 4-way ILP). Per-(thread,query) top-9 lives in local memory,
// touched only on the rare (~3.6%) improvement path via a while-loop insertion.
// Self is the provable max score -> keep top-9, drop idx==gq at merge.
#define KTILE 512
#define SQB 32
#define SSL 16
__global__ void __launch_bounds__(128) k_knn() {
    __shared__ __align__(16) char sbuf[36864];
    float4* sp  = (float4*)sbuf;              // phase A: [KTILE*2] = 16KB
    ull*    s9  = (ull*)(sbuf + 16384);       // phase A: [KTILE]   =  4KB
    float*  msc = (float*)sbuf;               // phase B: [128*4*9] = 18KB
    int*    mix = (int*)(sbuf + 18432);       // phase B: [128*4*9] = 18KB

    int t  = threadIdx.x;
    int s  = t >> 3;       // slice 0..15
    int qg = t & 7;        // query group 0..7
    int gqb = blockIdx.x * SQB + qg * 4;

    ull Q[4][4];
#pragma unroll
    for (int q = 0; q < 4; ++q) {
        float4 a = ((const float4*)g_h2)[(gqb + q) * 2];
        float4 b = ((const float4*)g_h2)[(gqb + q) * 2 + 1];
        Q[q][0] = pack2(a.x, a.y); Q[q][1] = pack2(a.z, a.w);
        Q[q][2] = pack2(b.x, b.y); Q[q][3] = pack2(b.z, b.w);
    }

    float l_sc[4][9]; int l_ix[4][9]; float thr[4];
#pragma unroll
    for (int q = 0; q < 4; ++q) {
        thr[q] = -INFINITY;
#pragma unroll
        for (int r = 0; r < 9; ++r) { l_sc[q][r] = -INFINITY; l_ix[q][r] = 0x7fffffff; }
    }

    for (int tb = 0; tb < NN; tb += KTILE) {
        __syncthreads();
        for (int v = t; v < KTILE; v += 128) {
            float4 a = ((const float4*)g_h2)[(tb + v) * 2];
            float4 b = ((const float4*)g_h2)[(tb + v) * 2 + 1];
            sp[v * 2] = a; sp[v * 2 + 1] = b;
            float sq = a.x * a.x + a.y * a.y + a.z * a.z + a.w * a.w +
                       b.x * b.x + b.y * b.y + b.z * b.z + b.w * b.w;
            float hh = -0.25f * sq;
            s9[v] = pack2(hh, hh);
        }
        __syncthreads();
        const ulonglong2* spu = (const ulonglong2*)sp;
        int jbase = s * (KTILE / SSL);
        for (int jj = 0; jj < KTILE / SSL; ++jj) {
            int jl = jbase + jj;
            ulonglong2 A = spu[jl * 2], B = spu[jl * 2 + 1];
            ull s9v = s9[jl];
            int idx = tb + jl;
#pragma unroll
            for (int q = 0; q < 4; ++q) {
                ull acc = ffma2(A.x, Q[q][0],
                          ffma2(A.y, Q[q][1],
                          ffma2(B.x, Q[q][2],
                          ffma2(B.y, Q[q][3], s9v))));
                float lo, hi; unpack2(lo, hi, acc);
                float sc = lo + hi;
                if (sc > thr[q]) {                           // rare
                    int r = 8;
                    while (r > 0 && l_sc[q][r - 1] < sc) {   // strict: idx-asc on ties
                        l_sc[q][r] = l_sc[q][r - 1];
                        l_ix[q][r] = l_ix[q][r - 1];
                        --r;
                    }
                    l_sc[q][r] = sc; l_ix[q][r] = idx;
                    thr[q] = l_sc[q][8];
                }
            }
        }
    }

    __syncthreads();
#pragma unroll
    for (int q = 0; q < 4; ++q)
#pragma unroll
        for (int r = 0; r < 9; ++r) {
            msc[(t * 4 + q) * 9 + r] = l_sc[q][r];
            mix[(t * 4 + q) * 9 + r] = l_ix[q][r];
        }
    __syncthreads();

    if (t < SQB) {
        // merge 16 sorted lists for query gq; score desc, idx asc; skip self.
        int mqg = t >> 2, mq = t & 3;
        int gq = blockIdx.x * SQB + t;   // == blockIdx.x*32 + mqg*4 + mq
        int p[SSL];
#pragma unroll
        for (int sl = 0; sl < SSL; ++sl) p[sl] = 0;
        int written = 0;
        for (int pick = 0; pick < 9 && written < 8; ++pick) {
            float bs = -INFINITY; int bi = 0x7fffffff; int bsl = 0;
#pragma unroll
            for (int sl = 0; sl < SSL; ++sl) {
                int base = ((sl * 8 + mqg) * 4 + mq) * 9 + p[sl];
                float v = msc[base]; int id = mix[base];
                if (v > bs || (v == bs && id < bi)) { bs = v; bi = id; bsl = sl; }
            }
#pragma unroll
            for (int sl = 0; sl < SSL; ++sl) p[sl] += (bsl == sl) ? 1 : 0;
            if (bi != gq) { g_knn[gq * 8 + written] = bi; ++written; }
        }
    }
}

// ---------------- conv3: h2[N,8] -> h3[N,8] over kNN edges (16->8 relu ->8) --
__global__ void k_conv3(const float* __restrict__ w1, const float* __restrict__ b1,
                        const float* __restrict__ w2, const float* __restrict__ b2) {
    __shared__ float sw1[128], sb1[8], sw2[64], sb2[8];
    int t = threadIdx.x;
    for (int v = t; v < 128; v += blockDim.x) sw1[v] = w1[v];
    for (int v = t; v < 64;  v += blockDim.x) sw2[v] = w2[v];
    if (t < 8) { sb1[t] = b1[t]; sb2[t] = b2[t]; }
    __syncthreads();
    int i = blockIdx.x * blockDim.x + t;
    float xi[8];
    {
        float4 a = ((const float4*)g_h2)[i * 2];
        float4 b = ((const float4*)g_h2)[i * 2 + 1];
        xi[0] = a.x; xi[1] = a.y; xi[2] = a.z; xi[3] = a.w;
        xi[4] = b.x; xi[5] = b.y; xi[6] = b.z; xi[7] = b.w;
    }
    float out[8];
#pragma unroll
    for (int o = 0; o < 8; ++o) out[o] = 0.0f;
#pragma unroll
    for (int n = 0; n < 8; ++n) {
        int j = g_knn[i * 8 + n];
        float4 c = ((const float4*)g_h2)[j * 2];
        float4 d = ((const float4*)g_h2)[j * 2 + 1];
        float xj[8] = { c.x, c.y, c.z, c.w, d.x, d.y, d.z, d.w };
        float h[8];
#pragma unroll
        for (int o = 0; o < 8; ++o) h[o] = sb1[o];
#pragma unroll
        for (int f = 0; f < 8; ++f) {
            float m0 = xi[f], m1 = xj[f] - xi[f];
#pragma unroll
            for (int o = 0; o < 8; ++o)
                h[o] += m0 * sw1[f * 8 + o] + m1 * sw1[(8 + f) * 8 + o];
        }
#pragma unroll
        for (int o = 0; o < 8; ++o) h[o] = fmaxf(h[o], 0.0f);
#pragma unroll
        for (int o = 0; o < 8; ++o) {
            float v = sb2[o];
#pragma unroll
            for (int f = 0; f < 8; ++f) v += h[f] * sw2[f * 8 + o];
            out[o] = fmaxf(out[o], v);
        }
    }
#pragma unroll
    for (int o = 0; o < 8; ++o) g_h3[i * 8 + o] = out[o];
}

// ---------------- conv4: h3[N,8] -> h4[N,16] over kNN edges (16->16 relu ->16)
__global__ void k_conv4(const float* __restrict__ w1, const float* __restrict__ b1,
                        const float* __restrict__ w2, const float* __restrict__ b2) {
    __shared__ float sw1[256], sb1[16], sw2[256], sb2[16];
    int t = threadIdx.x;
    for (int v = t; v < 256; v += blockDim.x) { sw1[v] = w1[v]; sw2[v] = w2[v]; }
    if (t < 16) { sb1[t] = b1[t]; sb2[t] = b2[t]; }
    __syncthreads();
    int i = blockIdx.x * blockDim.x + t;
    float xi[8];
    {
        float4 a = ((const float4*)g_h3)[i * 2];
        float4 b = ((const float4*)g_h3)[i * 2 + 1];
        xi[0] = a.x; xi[1] = a.y; xi[2] = a.z; xi[3] = a.w;
        xi[4] = b.x; xi[5] = b.y; xi[6] = b.z; xi[7] = b.w;
    }
    float out[16];
#pragma unroll
    for (int o = 0; o < 16; ++o) out[o] = 0.0f;
#pragma unroll
    for (int n = 0; n < 8; ++n) {
        int j = g_knn[i * 8 + n];
        float4 c = ((const float4*)g_h3)[j * 2];
        float4 d = ((const float4*)g_h3)[j * 2 + 1];
        float xj[8] = { c.x, c.y, c.z, c.w, d.x, d.y, d.z, d.w };
        float h[16];
#pragma unroll
        for (int o = 0; o < 16; ++o) h[o] = sb1[o];
#pragma unroll
        for (int f = 0; f < 8; ++f) {
            float m0 = xi[f], m1 = xj[f] - xi[f];
#pragma unroll
            for (int o = 0; o < 16; ++o)
                h[o] += m0 * sw1[f * 16 + o] + m1 * sw1[(8 + f) * 16 + o];
        }
#pragma unroll
        for (int o = 0; o < 16; ++o) h[o] = fmaxf(h[o], 0.0f);
#pragma unroll
        for (int o = 0; o < 16; ++o) {
            float v = sb2[o];
#pragma unroll
            for (int f = 0; f < 16; ++f) v += h[f] * sw2[f * 16 + o];
            out[o] = fmaxf(out[o], v);
        }
    }
#pragma unroll
    for (int o = 0; o < 16; ++o) g_h4[i * 16 + o] = out[o];
}

// ---------------- global max pool + MLP head + sigmoid -----------------------
__global__ void k_pool(const float* __restrict__ fw, const float* __restrict__ fb,
                       const float* __restrict__ ow, const float* __restrict__ ob,
                       float* __restrict__ out) {
    __shared__ float s[128 * 16];
    int g = blockIdx.x, t = threadIdx.x;
    int node = g * 128 + t;
#pragma unroll
    for (int f = 0; f < 16; ++f) s[t * 16 + f] = g_h4[node * 16 + f];
    __syncthreads();
    for (int st = 64; st > 0; st >>= 1) {
        if (t < st) {
#pragma unroll
            for (int f = 0; f < 16; ++f)
                s[t * 16 + f] = fmaxf(s[t * 16 + f], s[(t + st) * 16 + f]);
        }
        __syncthreads();
    }
    if (t == 0) {
        float z = ob[0];
#pragma unroll
        for (int o = 0; o < 6; ++o) {
            float y = fb[o];
#pragma unroll
            for (int f = 0; f < 16; ++f) y += s[f] * fw[f * 6 + o];
            z += fmaxf(y, 0.0f) * ow[o];
        }
        out[g] = 1.0f / (1.0f + expf(-z));
    }
}

// ---------------- launch ------------------------------------------------------
extern "C" void kernel_launch(void* const* d_in, const int* in_sizes, int n_in,
                              void* d_out, int out_size) {
    const float* x    = (const float*)d_in[0];
    const int*   ei   = (const int*)d_in[1];
    const float* c1w1 = (const float*)d_in[3];
    const float* c1b1 = (const float*)d_in[4];
    const float* c1w2 = (const float*)d_in[5];
    const float* c1b2 = (const float*)d_in[6];
    const float* c2w1 = (const float*)d_in[7];
    const float* c2b1 = (const float*)d_in[8];
    const float* c2w2 = (const float*)d_in[9];
    const float* c2b2 = (const float*)d_in[10];
    const float* c3w1 = (const float*)d_in[11];
    const float* c3b1 = (const float*)d_in[12];
    const float* c3w2 = (const float*)d_in[13];
    const float* c3b2 = (const float*)d_in[14];
    const float* c4w1 = (const float*)d_in[15];
    const float* c4b1 = (const float*)d_in[16];
    const float* c4w2 = (const float*)d_in[17];
    const float* c4b2 = (const float*)d_in[18];
    const float* fc3w = (const float*)d_in[19];
    const float* fc3b = (const float*)d_in[20];
    const float* outw = (const float*)d_in[21];
    const float* outb = (const float*)d_in[22];

    k_init <<< (NN * 16 + 255) / 256, 256 >>> ();
    k_conv1<<< E0C / 256, 256 >>>(x, ei, c1w1, c1b1, c1w2, c1b2);
    k_conv2<<< E0C / 256, 256 >>>(ei, c2w1, c2b1, c2w2, c2b2);
    k_knn  <<< NN / SQB, 128 >>>();
    k_conv3<<< NN / 128, 128 >>>(c3w1, c3b1, c3w2, c3b2);
    k_conv4<<< NN / 128, 128 >>>(c4w1, c4b1, c4w2, c4b2);
    k_pool <<< GG, 128 >>>(fc3w, fc3b, outw, outb, (float*)d_out);
}

// round 4
// speedup vs baseline: 6.8266x; 6.8266x over previous
#include <cuda_runtime.h>
#include <math.h>

#define NN 16384
#define GG 128
#define E0C 262144
#define KK 8

typedef unsigned long long ull;

// ---------------- scratch (device globals; no allocations allowed) ----------
__device__ float g_h1[NN * 16];
__device__ float g_h2[NN * 8];
__device__ int   g_knn[NN * KK];
__device__ float g_h3[NN * 8];
__device__ float g_h4[NN * 16];

// ---------------- packed f32x2 helpers (Blackwell FFMA2) ---------------------
__device__ __forceinline__ ull pack2(float lo, float hi) {
    ull r; asm("mov.b64 %0, {%1, %2};" : "=l"(r) : "f"(lo), "f"(hi)); return r;
}
__device__ __forceinline__ void unpack2(float& lo, float& hi, ull v) {
    asm("mov.b64 {%0, %1}, %2;" : "=f"(lo), "=f"(hi) : "l"(v));
}
__device__ __forceinline__ ull ffma2(ull a, ull b, ull c) {
    ull d; asm("fma.rn.f32x2 %0, %1, %2, %3;" : "=l"(d) : "l"(a), "l"(b), "l"(c));
    return d;
}

// ---------------- init: zero atomic-max accumulators ------------------------
__global__ void k_init() {
    int i = blockIdx.x * blockDim.x + threadIdx.x;
    if (i < NN * 16) g_h1[i] = 0.0f;
    if (i < NN * 8)  g_h2[i] = 0.0f;
}

// ---------------- conv1: x[N,3] -> h1[N,16] (6->16 relu ->16) ---------------
__global__ void k_conv1(const float* __restrict__ x, const int* __restrict__ ei,
                        const float* __restrict__ w1, const float* __restrict__ b1,
                        const float* __restrict__ w2, const float* __restrict__ b2) {
    __shared__ float sw1[96], sb1[16], sw2[256], sb2[16];
    int t = threadIdx.x;
    for (int v = t; v < 96;  v += blockDim.x) sw1[v] = w1[v];
    for (int v = t; v < 256; v += blockDim.x) sw2[v] = w2[v];
    if (t < 16) { sb1[t] = b1[t]; sb2[t] = b2[t]; }
    __syncthreads();
    int e = blockIdx.x * blockDim.x + t;
    if (e >= E0C) return;
    int s = ei[e], d = ei[E0C + e];
    float xi0 = x[d * 3], xi1 = x[d * 3 + 1], xi2 = x[d * 3 + 2];
    float m[6] = { xi0, xi1, xi2,
                   x[s * 3] - xi0, x[s * 3 + 1] - xi1, x[s * 3 + 2] - xi2 };
    float h[16];
#pragma unroll
    for (int o = 0; o < 16; ++o) h[o] = sb1[o];
#pragma unroll
    for (int i = 0; i < 6; ++i) {
        float mv = m[i];
#pragma unroll
        for (int o = 0; o < 16; ++o) h[o] += mv * sw1[i * 16 + o];
    }
#pragma unroll
    for (int o = 0; o < 16; ++o) h[o] = fmaxf(h[o], 0.0f);
    int* dst = (int*)&g_h1[d * 16];
#pragma unroll
    for (int o = 0; o < 16; ++o) {
        float v = sb2[o];
#pragma unroll
        for (int i = 0; i < 16; ++i) v += h[i] * sw2[i * 16 + o];
        atomicMax(dst + o, __float_as_int(fmaxf(v, 0.0f)));
    }
}

// ---------------- conv2: h1[N,16] -> h2[N,8] (32->8 relu ->8) ---------------
__global__ void k_conv2(const int* __restrict__ ei,
                        const float* __restrict__ w1, const float* __restrict__ b1,
                        const float* __restrict__ w2, const float* __restrict__ b2) {
    __shared__ float sw1[256], sb1[8], sw2[64], sb2[8];
    int t = threadIdx.x;
    for (int v = t; v < 256; v += blockDim.x) sw1[v] = w1[v];
    for (int v = t; v < 64;  v += blockDim.x) sw2[v] = w2[v];
    if (t < 8) { sb1[t] = b1[t]; sb2[t] = b2[t]; }
    __syncthreads();
    int e = blockIdx.x * blockDim.x + t;
    if (e >= E0C) return;
    int s = ei[e], d = ei[E0C + e];
    const float4* Xi = (const float4*)&g_h1[d * 16];
    const float4* Xj = (const float4*)&g_h1[s * 16];
    float xi[16], xj[16];
#pragma unroll
    for (int q = 0; q < 4; ++q) {
        float4 a = Xi[q], b = Xj[q];
        xi[q * 4 + 0] = a.x; xi[q * 4 + 1] = a.y; xi[q * 4 + 2] = a.z; xi[q * 4 + 3] = a.w;
        xj[q * 4 + 0] = b.x; xj[q * 4 + 1] = b.y; xj[q * 4 + 2] = b.z; xj[q * 4 + 3] = b.w;
    }
    float h[8];
#pragma unroll
    for (int o = 0; o < 8; ++o) h[o] = sb1[o];
#pragma unroll
    for (int f = 0; f < 16; ++f) {
        float m0 = xi[f], m1 = xj[f] - xi[f];
#pragma unroll
        for (int o = 0; o < 8; ++o)
            h[o] += m0 * sw1[f * 8 + o] + m1 * sw1[(16 + f) * 8 + o];
    }
#pragma unroll
    for (int o = 0; o < 8; ++o) h[o] = fmaxf(h[o], 0.0f);
    int* dst = (int*)&g_h2[d * 8];
#pragma unroll
    for (int o = 0; o < 8; ++o) {
        float v = sb2[o];
#pragma unroll
        for (int i = 0; i < 8; ++i) v += h[i] * sw2[i * 8 + o];
        atomicMax(dst + o, __float_as_int(fmaxf(v, 0.0f)));
    }
}

// ---------------- kNN --------------------------------------------------------
// Score s = dot(q,p) - 0.5|p|^2 (monotone in -distance). Lanes = queries,
// warps = point slices: every lane evaluates the SAME point pair -> all shared
// loads are warp-uniform broadcasts (zero bank conflicts, LDS amortized 64x).
// Point pairs staged as f32x2 records; one 8-deep FFMA2 chain (seeded with the
// packed -0.5|p|^2 values) yields both scores as a register pair.
// Per-lane top-9 in REGISTERS via fully-unrolled static-index bubble insert
// (no local memory), guarded by max(lo,hi) > thr. Self is provably the global
// max score -> keep 9, drop idx==gq at merge.
#define QB   32      // queries per block (one per lane)
#define SLC  8       // warps = point slices per block
#define KT   512     // tile points
#define RECB 80      // bytes per pair record (8 ull comps + s9 + pad)

#define KINS(c, id) do {                                                   \
    float _c = (c); int _i = (id);                                         \
    d8 = _c; x8 = _i;                                                      \
    if (_c > d7) { d8 = d7; x8 = x7; d7 = _c; x7 = _i;                     \
    if (_c > d6) { d7 = d6; x7 = x6; d6 = _c; x6 = _i;                     \
    if (_c > d5) { d6 = d5; x6 = x5; d5 = _c; x5 = _i;                     \
    if (_c > d4) { d5 = d4; x5 = x4; d4 = _c; x4 = _i;                     \
    if (_c > d3) { d4 = d3; x4 = x3; d3 = _c; x3 = _i;                     \
    if (_c > d2) { d3 = d2; x3 = x2; d2 = _c; x2 = _i;                     \
    if (_c > d1) { d2 = d1; x2 = x1; d1 = _c; x1 = _i;                     \
    if (_c > d0) { d1 = d0; x1 = x0; d0 = _c; x0 = _i; } } } } } } } }     \
    thr = d8;                                                              \
} while (0)

__global__ void __launch_bounds__(256) k_knn() {
    __shared__ __align__(16) char sbuf[20480];
    float* msc = (float*)sbuf;              // phase B: [32*8*9] floats = 9216B
    int*   mix = (int*)(sbuf + 9216);       // phase B: [32*8*9] ints   = 9216B

    int t = threadIdx.x;
    int w = t >> 5;          // slice warp 0..7
    int lane = t & 31;       // query lane
    int qb = blockIdx.x * QB;
    int gq = qb + lane;

    float4 qa = ((const float4*)g_h2)[gq * 2];
    float4 qc = ((const float4*)g_h2)[gq * 2 + 1];
    ull Q0 = pack2(qa.x, qa.x), Q1 = pack2(qa.y, qa.y);
    ull Q2 = pack2(qa.z, qa.z), Q3 = pack2(qa.w, qa.w);
    ull Q4 = pack2(qc.x, qc.x), Q5 = pack2(qc.y, qc.y);
    ull Q6 = pack2(qc.z, qc.z), Q7 = pack2(qc.w, qc.w);

    float d0 = -INFINITY, d1 = -INFINITY, d2 = -INFINITY, d3 = -INFINITY,
          d4 = -INFINITY, d5 = -INFINITY, d6 = -INFINITY, d7 = -INFINITY,
          d8 = -INFINITY;
    int x0 = 0x7fffffff, x1 = 0x7fffffff, x2 = 0x7fffffff, x3 = 0x7fffffff,
        x4 = 0x7fffffff, x5 = 0x7fffffff, x6 = 0x7fffffff, x7 = 0x7fffffff,
        x8 = 0x7fffffff;
    float thr = -INFINITY;

    for (int tb = 0; tb < NN; tb += KT) {
        __syncthreads();
        {   // stage one pair per thread (256 pairs)
            int p  = t;
            int j0 = tb + 2 * p;
            float4 a0 = ((const float4*)g_h2)[j0 * 2];
            float4 b0 = ((const float4*)g_h2)[j0 * 2 + 1];
            float4 a1 = ((const float4*)g_h2)[j0 * 2 + 2];
            float4 b1 = ((const float4*)g_h2)[j0 * 2 + 3];
            float sq0 = a0.x * a0.x + a0.y * a0.y + a0.z * a0.z + a0.w * a0.w +
                        b0.x * b0.x + b0.y * b0.y + b0.z * b0.z + b0.w * b0.w;
            float sq1 = a1.x * a1.x + a1.y * a1.y + a1.z * a1.z + a1.w * a1.w +
                        b1.x * b1.x + b1.y * b1.y + b1.z * b1.z + b1.w * b1.w;
            ulonglong2* rec = (ulonglong2*)(sbuf + p * RECB);
            ulonglong2 r0; r0.x = pack2(a0.x, a1.x); r0.y = pack2(a0.y, a1.y);
            ulonglong2 r1; r1.x = pack2(a0.z, a1.z); r1.y = pack2(a0.w, a1.w);
            ulonglong2 r2; r2.x = pack2(b0.x, b1.x); r2.y = pack2(b0.y, b1.y);
            ulonglong2 r3; r3.x = pack2(b0.z, b1.z); r3.y = pack2(b0.w, b1.w);
            rec[0] = r0; rec[1] = r1; rec[2] = r2; rec[3] = r3;
            *(ull*)(sbuf + p * RECB + 64) = pack2(-0.5f * sq0, -0.5f * sq1);
        }
        __syncthreads();
        // warp w scans pairs [w*32, w*32+32): identical address across lanes
#pragma unroll 2
        for (int pp = 0; pp < 32; ++pp) {
            const char* rec = sbuf + (w * 32 + pp) * RECB;
            ulonglong2 u01 = *(const ulonglong2*)(rec);
            ulonglong2 u23 = *(const ulonglong2*)(rec + 16);
            ulonglong2 u45 = *(const ulonglong2*)(rec + 32);
            ulonglong2 u67 = *(const ulonglong2*)(rec + 48);
            ull S = *(const ull*)(rec + 64);
            ull acc = ffma2(u01.x, Q0, ffma2(u01.y, Q1,
                      ffma2(u23.x, Q2, ffma2(u23.y, Q3,
                      ffma2(u45.x, Q4, ffma2(u45.y, Q5,
                      ffma2(u67.x, Q6, ffma2(u67.y, Q7, S))))))));
            float lo, hi; unpack2(lo, hi, acc);
            if (fmaxf(lo, hi) > thr) {
                int j0 = tb + (w * 32 + pp) * 2;
                if (lo > thr) { KINS(lo, j0); }
                if (hi > thr) { KINS(hi, j0 + 1); }
            }
        }
    }

    __syncthreads();
    {
        int b = (lane * SLC + w) * 9;
        msc[b + 0] = d0; msc[b + 1] = d1; msc[b + 2] = d2; msc[b + 3] = d3;
        msc[b + 4] = d4; msc[b + 5] = d5; msc[b + 6] = d6; msc[b + 7] = d7;
        msc[b + 8] = d8;
        mix[b + 0] = x0; mix[b + 1] = x1; mix[b + 2] = x2; mix[b + 3] = x3;
        mix[b + 4] = x4; mix[b + 5] = x5; mix[b + 6] = x6; mix[b + 7] = x7;
        mix[b + 8] = x8;
    }
    __syncthreads();

    if (t < QB) {
        // merge 8 sorted 9-deep lists for query qb+t; score desc, idx asc;
        // self (global max score) appears once -> skip it.
        int q = qb + t;
        int pos[SLC];
#pragma unroll
        for (int sl = 0; sl < SLC; ++sl) pos[sl] = 0;
        int written = 0;
        for (int pick = 0; pick < 9 && written < 8; ++pick) {
            float bs = -INFINITY; int bi = 0x7fffffff; int bw = 0;
#pragma unroll
            for (int sl = 0; sl < SLC; ++sl) {
                int b = (t * SLC + sl) * 9 + pos[sl];
                float v = msc[b]; int id = mix[b];
                if (v > bs || (v == bs && id < bi)) { bs = v; bi = id; bw = sl; }
            }
#pragma unroll
            for (int sl = 0; sl < SLC; ++sl) pos[sl] += (bw == sl) ? 1 : 0;
            if (bi != q) { g_knn[q * 8 + written] = bi; ++written; }
        }
    }
}

// ---------------- conv3: h2[N,8] -> h3[N,8] over kNN edges (16->8 relu ->8) --
__global__ void k_conv3(const float* __restrict__ w1, const float* __restrict__ b1,
                        const float* __restrict__ w2, const float* __restrict__ b2) {
    __shared__ float sw1[128], sb1[8], sw2[64], sb2[8];
    int t = threadIdx.x;
    for (int v = t; v < 128; v += blockDim.x) sw1[v] = w1[v];
    for (int v = t; v < 64;  v += blockDim.x) sw2[v] = w2[v];
    if (t < 8) { sb1[t] = b1[t]; sb2[t] = b2[t]; }
    __syncthreads();
    int i = blockIdx.x * blockDim.x + t;
    float xi[8];
    {
        float4 a = ((const float4*)g_h2)[i * 2];
        float4 b = ((const float4*)g_h2)[i * 2 + 1];
        xi[0] = a.x; xi[1] = a.y; xi[2] = a.z; xi[3] = a.w;
        xi[4] = b.x; xi[5] = b.y; xi[6] = b.z; xi[7] = b.w;
    }
    float out[8];
#pragma unroll
    for (int o = 0; o < 8; ++o) out[o] = 0.0f;
#pragma unroll
    for (int n = 0; n < 8; ++n) {
        int j = g_knn[i * 8 + n];
        float4 c = ((const float4*)g_h2)[j * 2];
        float4 d = ((const float4*)g_h2)[j * 2 + 1];
        float xj[8] = { c.x, c.y, c.z, c.w, d.x, d.y, d.z, d.w };
        float h[8];
#pragma unroll
        for (int o = 0; o < 8; ++o) h[o] = sb1[o];
#pragma unroll
        for (int f = 0; f < 8; ++f) {
            float m0 = xi[f], m1 = xj[f] - xi[f];
#pragma unroll
            for (int o = 0; o < 8; ++o)
                h[o] += m0 * sw1[f * 8 + o] + m1 * sw1[(8 + f) * 8 + o];
        }
#pragma unroll
        for (int o = 0; o < 8; ++o) h[o] = fmaxf(h[o], 0.0f);
#pragma unroll
        for (int o = 0; o < 8; ++o) {
            float v = sb2[o];
#pragma unroll
            for (int f = 0; f < 8; ++f) v += h[f] * sw2[f * 8 + o];
            out[o] = fmaxf(out[o], v);
        }
    }
#pragma unroll
    for (int o = 0; o < 8; ++o) g_h3[i * 8 + o] = out[o];
}

// ---------------- conv4: h3[N,8] -> h4[N,16] over kNN edges (16->16 relu ->16)
__global__ void k_conv4(const float* __restrict__ w1, const float* __restrict__ b1,
                        const float* __restrict__ w2, const float* __restrict__ b2) {
    __shared__ float sw1[256], sb1[16], sw2[256], sb2[16];
    int t = threadIdx.x;
    for (int v = t; v < 256; v += blockDim.x) { sw1[v] = w1[v]; sw2[v] = w2[v]; }
    if (t < 16) { sb1[t] = b1[t]; sb2[t] = b2[t]; }
    __syncthreads();
    int i = blockIdx.x * blockDim.x + t;
    float xi[8];
    {
        float4 a = ((const float4*)g_h3)[i * 2];
        float4 b = ((const float4*)g_h3)[i * 2 + 1];
        xi[0] = a.x; xi[1] = a.y; xi[2] = a.z; xi[3] = a.w;
        xi[4] = b.x; xi[5] = b.y; xi[6] = b.z; xi[7] = b.w;
    }
    float out[16];
#pragma unroll
    for (int o = 0; o < 16; ++o) out[o] = 0.0f;
#pragma unroll
    for (int n = 0; n < 8; ++n) {
        int j = g_knn[i * 8 + n];
        float4 c = ((const float4*)g_h3)[j * 2];
        float4 d = ((const float4*)g_h3)[j * 2 + 1];
        float xj[8] = { c.x, c.y, c.z, c.w, d.x, d.y, d.z, d.w };
        float h[16];
#pragma unroll
        for (int o = 0; o < 16; ++o) h[o] = sb1[o];
#pragma unroll
        for (int f = 0; f < 8; ++f) {
            float m0 = xi[f], m1 = xj[f] - xi[f];
#pragma unroll
            for (int o = 0; o < 16; ++o)
                h[o] += m0 * sw1[f * 16 + o] + m1 * sw1[(8 + f) * 16 + o];
        }
#pragma unroll
        for (int o = 0; o < 16; ++o) h[o] = fmaxf(h[o], 0.0f);
#pragma unroll
        for (int o = 0; o < 16; ++o) {
            float v = sb2[o];
#pragma unroll
            for (int f = 0; f < 16; ++f) v += h[f] * sw2[f * 16 + o];
            out[o] = fmaxf(out[o], v);
        }
    }
#pragma unroll
    for (int o = 0; o < 16; ++o) g_h4[i * 16 + o] = out[o];
}

// ---------------- global max pool + MLP head + sigmoid -----------------------
__global__ void k_pool(const float* __restrict__ fw, const float* __restrict__ fb,
                       const float* __restrict__ ow, const float* __restrict__ ob,
                       float* __restrict__ out) {
    __shared__ float s[128 * 16];
    int g = blockIdx.x, t = threadIdx.x;
    int node = g * 128 + t;
#pragma unroll
    for (int f = 0; f < 16; ++f) s[t * 16 + f] = g_h4[node * 16 + f];
    __syncthreads();
    for (int st = 64; st > 0; st >>= 1) {
        if (t < st) {
#pragma unroll
            for (int f = 0; f < 16; ++f)
                s[t * 16 + f] = fmaxf(s[t * 16 + f], s[(t + st) * 16 + f]);
        }
        __syncthreads();
    }
    if (t == 0) {
        float z = ob[0];
#pragma unroll
        for (int o = 0; o < 6; ++o) {
            float y = fb[o];
#pragma unroll
            for (int f = 0; f < 16; ++f) y += s[f] * fw[f * 6 + o];
            z += fmaxf(y, 0.0f) * ow[o];
        }
        out[g] = 1.0f / (1.0f + expf(-z));
    }
}

// ---------------- launch ------------------------------------------------------
extern "C" void kernel_launch(void* const* d_in, const int* in_sizes, int n_in,
                              void* d_out, int out_size) {
    const float* x    = (const float*)d_in[0];
    const int*   ei   = (const int*)d_in[1];
    const float* c1w1 = (const float*)d_in[3];
    const float* c1b1 = (const float*)d_in[4];
    const float* c1w2 = (const float*)d_in[5];
    const float* c1b2 = (const float*)d_in[6];
    const float* c2w1 = (const float*)d_in[7];
    const float* c2b1 = (const float*)d_in[8];
    const float* c2w2 = (const float*)d_in[9];
    const float* c2b2 = (const float*)d_in[10];
    const float* c3w1 = (const float*)d_in[11];
    const float* c3b1 = (const float*)d_in[12];
    const float* c3w2 = (const float*)d_in[13];
    const float* c3b2 = (const float*)d_in[14];
    const float* c4w1 = (const float*)d_in[15];
    const float* c4b1 = (const float*)d_in[16];
    const float* c4w2 = (const float*)d_in[17];
    const float* c4b2 = (const float*)d_in[18];
    const float* fc3w = (const float*)d_in[19];
    const float* fc3b = (const float*)d_in[20];
    const float* outw = (const float*)d_in[21];
    const float* outb = (const float*)d_in[22];

    k_init <<< (NN * 16 + 255) / 256, 256 >>> ();
    k_conv1<<< E0C / 256, 256 >>>(x, ei, c1w1, c1b1, c1w2, c1b2);
    k_conv2<<< E0C / 256, 256 >>>(ei, c2w1, c2b1, c2w2, c2b2);
    k_knn  <<< NN / QB, 256 >>>();
    k_conv3<<< NN / 128, 128 >>>(c3w1, c3b1, c3w2, c3b2);
    k_conv4<<< NN / 128, 128 >>>(c4w1, c4b1, c4w2, c4b2);
    k_pool <<< GG, 128 >>>(fc3w, fc3b, outw, outb, (float*)d_out);
}

// round 5
// speedup vs baseline: 9.4810x; 1.3888x over previous
#include <cuda_runtime.h>
#include <math.h>

#define NN 16384
#define GG 128
#define E0C 262144
#define KK 8

// ---------------- scratch (device globals; no allocations allowed) ----------
__device__ float g_h1[NN * 16];
__device__ float g_h2[NN * 8];
__device__ int   g_knn[NN * KK];
__device__ float g_h3[NN * 8];
__device__ float g_h4[NN * 16];

// ---------------- init: zero atomic-max accumulators ------------------------
__global__ void k_init() {
    int i = blockIdx.x * blockDim.x + threadIdx.x;
    if (i < NN * 16) g_h1[i] = 0.0f;
    if (i < NN * 8)  g_h2[i] = 0.0f;
}

// ---------------- conv1: x[N,3] -> h1[N,16] (6->16 relu ->16) ---------------
__global__ void k_conv1(const float* __restrict__ x, const int* __restrict__ ei,
                        const float* __restrict__ w1, const float* __restrict__ b1,
                        const float* __restrict__ w2, const float* __restrict__ b2) {
    __shared__ float sw1[96], sb1[16], sw2[256], sb2[16];
    int t = threadIdx.x;
    for (int v = t; v < 96;  v += blockDim.x) sw1[v] = w1[v];
    for (int v = t; v < 256; v += blockDim.x) sw2[v] = w2[v];
    if (t < 16) { sb1[t] = b1[t]; sb2[t] = b2[t]; }
    __syncthreads();
    int e = blockIdx.x * blockDim.x + t;
    if (e >= E0C) return;
    int s = ei[e], d = ei[E0C + e];
    float xi0 = x[d * 3], xi1 = x[d * 3 + 1], xi2 = x[d * 3 + 2];
    float m[6] = { xi0, xi1, xi2,
                   x[s * 3] - xi0, x[s * 3 + 1] - xi1, x[s * 3 + 2] - xi2 };
    float h[16];
#pragma unroll
    for (int o = 0; o < 16; ++o) h[o] = sb1[o];
#pragma unroll
    for (int i = 0; i < 6; ++i) {
        float mv = m[i];
#pragma unroll
        for (int o = 0; o < 16; ++o) h[o] += mv * sw1[i * 16 + o];
    }
#pragma unroll
    for (int o = 0; o < 16; ++o) h[o] = fmaxf(h[o], 0.0f);
    int* dst = (int*)&g_h1[d * 16];
#pragma unroll
    for (int o = 0; o < 16; ++o) {
        float v = sb2[o];
#pragma unroll
        for (int i = 0; i < 16; ++i) v += h[i] * sw2[i * 16 + o];
        atomicMax(dst + o, __float_as_int(fmaxf(v, 0.0f)));
    }
}

// ---------------- conv2: h1[N,16] -> h2[N,8] (32->8 relu ->8) ---------------
__global__ void k_conv2(const int* __restrict__ ei,
                        const float* __restrict__ w1, const float* __restrict__ b1,
                        const float* __restrict__ w2, const float* __restrict__ b2) {
    __shared__ float sw1[256], sb1[8], sw2[64], sb2[8];
    int t = threadIdx.x;
    for (int v = t; v < 256; v += blockDim.x) sw1[v] = w1[v];
    for (int v = t; v < 64;  v += blockDim.x) sw2[v] = w2[v];
    if (t < 8) { sb1[t] = b1[t]; sb2[t] = b2[t]; }
    __syncthreads();
    int e = blockIdx.x * blockDim.x + t;
    if (e >= E0C) return;
    int s = ei[e], d = ei[E0C + e];
    const float4* Xi = (const float4*)&g_h1[d * 16];
    const float4* Xj = (const float4*)&g_h1[s * 16];
    float xi[16], xj[16];
#pragma unroll
    for (int q = 0; q < 4; ++q) {
        float4 a = Xi[q], b = Xj[q];
        xi[q * 4 + 0] = a.x; xi[q * 4 + 1] = a.y; xi[q * 4 + 2] = a.z; xi[q * 4 + 3] = a.w;
        xj[q * 4 + 0] = b.x; xj[q * 4 + 1] = b.y; xj[q * 4 + 2] = b.z; xj[q * 4 + 3] = b.w;
    }
    float h[8];
#pragma unroll
    for (int o = 0; o < 8; ++o) h[o] = sb1[o];
#pragma unroll
    for (int f = 0; f < 16; ++f) {
        float m0 = xi[f], m1 = xj[f] - xi[f];
#pragma unroll
        for (int o = 0; o < 8; ++o)
            h[o] += m0 * sw1[f * 8 + o] + m1 * sw1[(16 + f) * 8 + o];
    }
#pragma unroll
    for (int o = 0; o < 8; ++o) h[o] = fmaxf(h[o], 0.0f);
    int* dst = (int*)&g_h2[d * 8];
#pragma unroll
    for (int o = 0; o < 8; ++o) {
        float v = sb2[o];
#pragma unroll
        for (int i = 0; i < 8; ++i) v += h[i] * sw2[i * 8 + o];
        atomicMax(dst + o, __float_as_int(fmaxf(v, 0.0f)));
    }
}

// ---------------- kNN --------------------------------------------------------
// Score s = dot(q,p) - 0.5|p|^2 (monotone in -distance; sq_i cancels).
// Lanes = queries, warps = point slices: every lane evaluates the SAME point,
// so all shared reads are warp-uniform broadcasts (conflict-free, amortized
// 32x). Scalar 8-FFMA chain per point (f32x2 splits on sm_100a -> no benefit).
// Per-lane top-9 kept as UNSORTED register slots: on the rare hit, overwrite
// the slot equal to thr, recompute thr with 8 FMNMX (no sorted-shift ALU).
// Self is provably the global max score -> keep 9, drop idx==gq at merge.
// Merge: dump raw 8x9 candidates per query, selection with (score desc,
// idx asc) + mark-used; every point evaluated exactly once -> no duplicates.
#define QB   32      // queries per block (one per lane)
#define KT   512     // tile points
#define RECB 48      // 2*float4 comps + norm + pad

#define INS9(sc, id) do {                                                     \
    float _c = (sc); int _i = (id);                                           \
    bool _r = (s0 == thr);            if (_r)  { s0 = _c; i0 = _i; }          \
    bool _n = !_r && (s1 == thr);     if (_n)  { s1 = _c; i1 = _i; } _r |= _n;\
    _n = !_r && (s2 == thr);          if (_n)  { s2 = _c; i2 = _i; } _r |= _n;\
    _n = !_r && (s3 == thr);          if (_n)  { s3 = _c; i3 = _i; } _r |= _n;\
    _n = !_r && (s4 == thr);          if (_n)  { s4 = _c; i4 = _i; } _r |= _n;\
    _n = !_r && (s5 == thr);          if (_n)  { s5 = _c; i5 = _i; } _r |= _n;\
    _n = !_r && (s6 == thr);          if (_n)  { s6 = _c; i6 = _i; } _r |= _n;\
    _n = !_r && (s7 == thr);          if (_n)  { s7 = _c; i7 = _i; } _r |= _n;\
    _n = !_r;                         if (_n)  { s8 = _c; i8 = _i; }          \
    thr = fminf(fminf(fminf(fminf(s0, s1), fminf(s2, s3)),                    \
                      fminf(fminf(s4, s5), fminf(s6, s7))), s8);              \
} while (0)

__global__ void __launch_bounds__(256) k_knn() {
    __shared__ __align__(16) char sbuf[24576];
    // phase A: KT records of 48B (2 float4 + norm)
    // phase B: msc[32*72] floats (9216B) + mix[32*72] ints (9216B)
    float* msc = (float*)sbuf;
    int*   mix = (int*)(sbuf + 9216);

    int t = threadIdx.x;
    int w = t >> 5;          // slice warp 0..7
    int lane = t & 31;       // query lane
    int qb = blockIdx.x * QB;
    int gq = qb + lane;

    float4 qa = ((const float4*)g_h2)[gq * 2];
    float4 qc = ((const float4*)g_h2)[gq * 2 + 1];
    float q0 = qa.x, q1 = qa.y, q2 = qa.z, q3 = qa.w;
    float q4 = qc.x, q5 = qc.y, q6 = qc.z, q7 = qc.w;

    float s0 = -INFINITY, s1 = -INFINITY, s2 = -INFINITY, s3 = -INFINITY,
          s4 = -INFINITY, s5 = -INFINITY, s6 = -INFINITY, s7 = -INFINITY,
          s8 = -INFINITY;
    int i0 = 0, i1 = 0, i2 = 0, i3 = 0, i4 = 0, i5 = 0, i6 = 0, i7 = 0, i8 = 0;
    float thr = -INFINITY;

    for (int tb = 0; tb < NN; tb += KT) {
        __syncthreads();
#pragma unroll
        for (int v = t; v < KT; v += 256) {
            float4 a = ((const float4*)g_h2)[(tb + v) * 2];
            float4 b = ((const float4*)g_h2)[(tb + v) * 2 + 1];
            char* rec = sbuf + v * RECB;
            *(float4*)rec        = a;
            *(float4*)(rec + 16) = b;
            float sq = a.x * a.x + a.y * a.y + a.z * a.z + a.w * a.w +
                       b.x * b.x + b.y * b.y + b.z * b.z + b.w * b.w;
            *(float*)(rec + 32) = -0.5f * sq;
        }
        __syncthreads();
        // warp w scans points [w*64, w*64+64): identical address across lanes
        const char* rec = sbuf + (w << 6) * RECB;
#pragma unroll 4
        for (int pp = 0; pp < 64; ++pp) {
            float4 A = *(const float4*)(rec);
            float4 B = *(const float4*)(rec + 16);
            float  n = *(const float*)(rec + 32);
            rec += RECB;
            float acc = fmaf(A.x, q0, fmaf(A.y, q1, fmaf(A.z, q2, fmaf(A.w, q3,
                        fmaf(B.x, q4, fmaf(B.y, q5, fmaf(B.z, q6, fmaf(B.w, q7, n))))))));
            if (acc > thr) {
                int j = tb + (w << 6) + pp;
                INS9(acc, j);
            }
        }
    }

    __syncthreads();
    {
        int b = lane * 72 + w * 9;
        msc[b + 0] = s0; msc[b + 1] = s1; msc[b + 2] = s2; msc[b + 3] = s3;
        msc[b + 4] = s4; msc[b + 5] = s5; msc[b + 6] = s6; msc[b + 7] = s7;
        msc[b + 8] = s8;
        mix[b + 0] = i0; mix[b + 1] = i1; mix[b + 2] = i2; mix[b + 3] = i3;
        mix[b + 4] = i4; mix[b + 5] = i5; mix[b + 6] = i6; mix[b + 7] = i7;
        mix[b + 8] = i8;
    }
    __syncthreads();

    if (t < QB) {
        // select top-8 of 72 candidates for query qb+t (score desc, idx asc),
        // skipping self (the global max, present exactly once). No duplicates.
        int q = qb + t;
        int written = 0;
        for (int pick = 0; pick < 9 && written < 8; ++pick) {
            float bs = -INFINITY; int bi = 0x7fffffff; int bp = 0;
            for (int e = 0; e < 72; ++e) {
                float v = msc[t * 72 + e]; int id = mix[t * 72 + e];
                if (v > bs || (v == bs && id < bi)) { bs = v; bi = id; bp = e; }
            }
            msc[t * 72 + bp] = -INFINITY;
            if (bi != q) { g_knn[q * 8 + written] = bi; ++written; }
        }
    }
}

// ---------------- conv3: h2[N,8] -> h3[N,8] over kNN edges (16->8 relu ->8) --
__global__ void k_conv3(const float* __restrict__ w1, const float* __restrict__ b1,
                        const float* __restrict__ w2, const float* __restrict__ b2) {
    __shared__ float sw1[128], sb1[8], sw2[64], sb2[8];
    int t = threadIdx.x;
    for (int v = t; v < 128; v += blockDim.x) sw1[v] = w1[v];
    for (int v = t; v < 64;  v += blockDim.x) sw2[v] = w2[v];
    if (t < 8) { sb1[t] = b1[t]; sb2[t] = b2[t]; }
    __syncthreads();
    int i = blockIdx.x * blockDim.x + t;
    float xi[8];
    {
        float4 a = ((const float4*)g_h2)[i * 2];
        float4 b = ((const float4*)g_h2)[i * 2 + 1];
        xi[0] = a.x; xi[1] = a.y; xi[2] = a.z; xi[3] = a.w;
        xi[4] = b.x; xi[5] = b.y; xi[6] = b.z; xi[7] = b.w;
    }
    float out[8];
#pragma unroll
    for (int o = 0; o < 8; ++o) out[o] = 0.0f;
#pragma unroll
    for (int n = 0; n < 8; ++n) {
        int j = g_knn[i * 8 + n];
        float4 c = ((const float4*)g_h2)[j * 2];
        float4 d = ((const float4*)g_h2)[j * 2 + 1];
        float xj[8] = { c.x, c.y, c.z, c.w, d.x, d.y, d.z, d.w };
        float h[8];
#pragma unroll
        for (int o = 0; o < 8; ++o) h[o] = sb1[o];
#pragma unroll
        for (int f = 0; f < 8; ++f) {
            float m0 = xi[f], m1 = xj[f] - xi[f];
#pragma unroll
            for (int o = 0; o < 8; ++o)
                h[o] += m0 * sw1[f * 8 + o] + m1 * sw1[(8 + f) * 8 + o];
        }
#pragma unroll
        for (int o = 0; o < 8; ++o) h[o] = fmaxf(h[o], 0.0f);
#pragma unroll
        for (int o = 0; o < 8; ++o) {
            float v = sb2[o];
#pragma unroll
            for (int f = 0; f < 8; ++f) v += h[f] * sw2[f * 8 + o];
            out[o] = fmaxf(out[o], v);
        }
    }
#pragma unroll
    for (int o = 0; o < 8; ++o) g_h3[i * 8 + o] = out[o];
}

// ---------------- conv4: h3[N,8] -> h4[N,16] over kNN edges (16->16 relu ->16)
__global__ void k_conv4(const float* __restrict__ w1, const float* __restrict__ b1,
                        const float* __restrict__ w2, const float* __restrict__ b2) {
    __shared__ float sw1[256], sb1[16], sw2[256], sb2[16];
    int t = threadIdx.x;
    for (int v = t; v < 256; v += blockDim.x) { sw1[v] = w1[v]; sw2[v] = w2[v]; }
    if (t < 16) { sb1[t] = b1[t]; sb2[t] = b2[t]; }
    __syncthreads();
    int i = blockIdx.x * blockDim.x + t;
    float xi[8];
    {
        float4 a = ((const float4*)g_h3)[i * 2];
        float4 b = ((const float4*)g_h3)[i * 2 + 1];
        xi[0] = a.x; xi[1] = a.y; xi[2] = a.z; xi[3] = a.w;
        xi[4] = b.x; xi[5] = b.y; xi[6] = b.z; xi[7] = b.w;
    }
    float out[16];
#pragma unroll
    for (int o = 0; o < 16; ++o) out[o] = 0.0f;
#pragma unroll
    for (int n = 0; n < 8; ++n) {
        int j = g_knn[i * 8 + n];
        float4 c = ((const float4*)g_h3)[j * 2];
        float4 d = ((const float4*)g_h3)[j * 2 + 1];
        float xj[8] = { c.x, c.y, c.z, c.w, d.x, d.y, d.z, d.w };
        float h[16];
#pragma unroll
        for (int o = 0; o < 16; ++o) h[o] = sb1[o];
#pragma unroll
        for (int f = 0; f < 8; ++f) {
            float m0 = xi[f], m1 = xj[f] - xi[f];
#pragma unroll
            for (int o = 0; o < 16; ++o)
                h[o] += m0 * sw1[f * 16 + o] + m1 * sw1[(8 + f) * 16 + o];
        }
#pragma unroll
        for (int o = 0; o < 16; ++o) h[o] = fmaxf(h[o], 0.0f);
#pragma unroll
        for (int o = 0; o < 16; ++o) {
            float v = sb2[o];
#pragma unroll
            for (int f = 0; f < 16; ++f) v += h[f] * sw2[f * 16 + o];
            out[o] = fmaxf(out[o], v);
        }
    }
#pragma unroll
    for (int o = 0; o < 16; ++o) g_h4[i * 16 + o] = out[o];
}

// ---------------- global max pool + MLP head + sigmoid -----------------------
__global__ void k_pool(const float* __restrict__ fw, const float* __restrict__ fb,
                       const float* __restrict__ ow, const float* __restrict__ ob,
                       float* __restrict__ out) {
    __shared__ float s[128 * 16];
    int g = blockIdx.x, t = threadIdx.x;
    int node = g * 128 + t;
#pragma unroll
    for (int f = 0; f < 16; ++f) s[t * 16 + f] = g_h4[node * 16 + f];
    __syncthreads();
    for (int st = 64; st > 0; st >>= 1) {
        if (t < st) {
#pragma unroll
            for (int f = 0; f < 16; ++f)
                s[t * 16 + f] = fmaxf(s[t * 16 + f], s[(t + st) * 16 + f]);
        }
        __syncthreads();
    }
    if (t == 0) {
        float z = ob[0];
#pragma unroll
        for (int o = 0; o < 6; ++o) {
            float y = fb[o];
#pragma unroll
            for (int f = 0; f < 16; ++f) y += s[f] * fw[f * 6 + o];
            z += fmaxf(y, 0.0f) * ow[o];
        }
        out[g] = 1.0f / (1.0f + expf(-z));
    }
}

// ---------------- launch ------------------------------------------------------
extern "C" void kernel_launch(void* const* d_in, const int* in_sizes, int n_in,
                              void* d_out, int out_size) {
    const float* x    = (const float*)d_in[0];
    const int*   ei   = (const int*)d_in[1];
    const float* c1w1 = (const float*)d_in[3];
    const float* c1b1 = (const float*)d_in[4];
    const float* c1w2 = (const float*)d_in[5];
    const float* c1b2 = (const float*)d_in[6];
    const float* c2w1 = (const float*)d_in[7];
    const float* c2b1 = (const float*)d_in[8];
    const float* c2w2 = (const float*)d_in[9];
    const float* c2b2 = (const float*)d_in[10];
    const float* c3w1 = (const float*)d_in[11];
    const float* c3b1 = (const float*)d_in[12];
    const float* c3w2 = (const float*)d_in[13];
    const float* c3b2 = (const float*)d_in[14];
    const float* c4w1 = (const float*)d_in[15];
    const float* c4b1 = (const float*)d_in[16];
    const float* c4w2 = (const float*)d_in[17];
    const float* c4b2 = (const float*)d_in[18];
    const float* fc3w = (const float*)d_in[19];
    const float* fc3b = (const float*)d_in[20];
    const float* outw = (const float*)d_in[21];
    const float* outb = (const float*)d_in[22];

    k_init <<< (NN * 16 + 255) / 256, 256 >>> ();
    k_conv1<<< E0C / 256, 256 >>>(x, ei, c1w1, c1b1, c1w2, c1b2);
    k_conv2<<< E0C / 256, 256 >>>(ei, c2w1, c2b1, c2w2, c2b2);
    k_knn  <<< NN / QB, 256 >>>();
    k_conv3<<< NN / 128, 128 >>>(c3w1, c3b1, c3w2, c3b2);
    k_conv4<<< NN / 128, 128 >>>(c4w1, c4b1, c4w2, c4b2);
    k_pool <<< GG, 128 >>>(fc3w, fc3b, outw, outb, (float*)d_out);
}

// round 6
// speedup vs baseline: 10.9615x; 1.1562x over previous
#include <cuda_runtime.h>
#include <math.h>

#define NN 16384
#define GG 128
#define E0C 262144
#define KK 8

typedef unsigned long long ull;

// ---------------- scratch (device globals; no allocations allowed) ----------
__device__ float g_h1[NN * 16];
__device__ float g_h2[NN * 8];
__device__ int   g_knn[NN * KK];
__device__ float g_h3[NN * 8];
__device__ float g_h4[NN * 16];

// ---------------- init: zero atomic-max accumulators ------------------------
__global__ void k_init() {
    int i = blockIdx.x * blockDim.x + threadIdx.x;
    if (i < NN * 16) g_h1[i] = 0.0f;
    if (i < NN * 8)  g_h2[i] = 0.0f;
}

// ---------------- conv1: x[N,3] -> h1[N,16] (6->16 relu ->16) ---------------
__global__ void k_conv1(const float* __restrict__ x, const int* __restrict__ ei,
                        const float* __restrict__ w1, const float* __restrict__ b1,
                        const float* __restrict__ w2, const float* __restrict__ b2) {
    __shared__ float sw1[96], sb1[16], sw2[256], sb2[16];
    int t = threadIdx.x;
    for (int v = t; v < 96;  v += blockDim.x) sw1[v] = w1[v];
    for (int v = t; v < 256; v += blockDim.x) sw2[v] = w2[v];
    if (t < 16) { sb1[t] = b1[t]; sb2[t] = b2[t]; }
    __syncthreads();
    int e = blockIdx.x * blockDim.x + t;
    if (e >= E0C) return;
    int s = ei[e], d = ei[E0C + e];
    float xi0 = x[d * 3], xi1 = x[d * 3 + 1], xi2 = x[d * 3 + 2];
    float m[6] = { xi0, xi1, xi2,
                   x[s * 3] - xi0, x[s * 3 + 1] - xi1, x[s * 3 + 2] - xi2 };
    float h[16];
#pragma unroll
    for (int o = 0; o < 16; ++o) h[o] = sb1[o];
#pragma unroll
    for (int i = 0; i < 6; ++i) {
        float mv = m[i];
#pragma unroll
        for (int o = 0; o < 16; ++o) h[o] += mv * sw1[i * 16 + o];
    }
#pragma unroll
    for (int o = 0; o < 16; ++o) h[o] = fmaxf(h[o], 0.0f);
    int* dst = (int*)&g_h1[d * 16];
#pragma unroll
    for (int o = 0; o < 16; ++o) {
        float v = sb2[o];
#pragma unroll
        for (int i = 0; i < 16; ++i) v += h[i] * sw2[i * 16 + o];
        atomicMax(dst + o, __float_as_int(fmaxf(v, 0.0f)));
    }
}

// ---------------- conv2: h1[N,16] -> h2[N,8] (32->8 relu ->8) ---------------
__global__ void k_conv2(const int* __restrict__ ei,
                        const float* __restrict__ w1, const float* __restrict__ b1,
                        const float* __restrict__ w2, const float* __restrict__ b2) {
    __shared__ float sw1[256], sb1[8], sw2[64], sb2[8];
    int t = threadIdx.x;
    for (int v = t; v < 256; v += blockDim.x) sw1[v] = w1[v];
    for (int v = t; v < 64;  v += blockDim.x) sw2[v] = w2[v];
    if (t < 8) { sb1[t] = b1[t]; sb2[t] = b2[t]; }
    __syncthreads();
    int e = blockIdx.x * blockDim.x + t;
    if (e >= E0C) return;
    int s = ei[e], d = ei[E0C + e];
    const float4* Xi = (const float4*)&g_h1[d * 16];
    const float4* Xj = (const float4*)&g_h1[s * 16];
    float xi[16], xj[16];
#pragma unroll
    for (int q = 0; q < 4; ++q) {
        float4 a = Xi[q], b = Xj[q];
        xi[q * 4 + 0] = a.x; xi[q * 4 + 1] = a.y; xi[q * 4 + 2] = a.z; xi[q * 4 + 3] = a.w;
        xj[q * 4 + 0] = b.x; xj[q * 4 + 1] = b.y; xj[q * 4 + 2] = b.z; xj[q * 4 + 3] = b.w;
    }
    float h[8];
#pragma unroll
    for (int o = 0; o < 8; ++o) h[o] = sb1[o];
#pragma unroll
    for (int f = 0; f < 16; ++f) {
        float m0 = xi[f], m1 = xj[f] - xi[f];
#pragma unroll
        for (int o = 0; o < 8; ++o)
            h[o] += m0 * sw1[f * 8 + o] + m1 * sw1[(16 + f) * 8 + o];
    }
#pragma unroll
    for (int o = 0; o < 8; ++o) h[o] = fmaxf(h[o], 0.0f);
    int* dst = (int*)&g_h2[d * 8];
#pragma unroll
    for (int o = 0; o < 8; ++o) {
        float v = sb2[o];
#pragma unroll
        for (int i = 0; i < 8; ++i) v += h[i] * sw2[i * 8 + o];
        atomicMax(dst + o, __float_as_int(fmaxf(v, 0.0f)));
    }
}

// ---------------- kNN --------------------------------------------------------
// Score s = dot(q,p) - 0.5|p|^2 (monotone in -distance; sq_i cancels).
// Lanes = queries, warps = point slices; point reads are warp-uniform
// broadcasts. HOT PATH: 8 FFMA + guard + 2-op predicated push of (score,idx)
// into a per-lane shared stack. The exact top-9 maintenance (INS9) runs only
// in rare whole-warp DRAINs (vote.any(cnt>=9), checked every 2nd iteration).
// thr staleness between drains only adds pushes (never drops candidates);
// each point pushed at most once -> exactness preserved.
// Self is provably the global max score -> keep 9, drop idx==gq at merge.
#define QB   32      // queries per block (one per lane)
#define KT   512     // tile points
#define RECB 48      // 2*float4 comps + norm + pad
#define BCAP 10      // buffer slots per lane (trigger >=9, checked every 2)
#define BUFOFF 24576 // records occupy [0, 24576)

#define INS9(sc, id) do {                                                     \
    float _c = (sc); int _i = (id);                                           \
    bool _r = (s0 == thr);            if (_r)  { s0 = _c; i0 = _i; }          \
    bool _n = !_r && (s1 == thr);     if (_n)  { s1 = _c; i1 = _i; } _r |= _n;\
    _n = !_r && (s2 == thr);          if (_n)  { s2 = _c; i2 = _i; } _r |= _n;\
    _n = !_r && (s3 == thr);          if (_n)  { s3 = _c; i3 = _i; } _r |= _n;\
    _n = !_r && (s4 == thr);          if (_n)  { s4 = _c; i4 = _i; } _r |= _n;\
    _n = !_r && (s5 == thr);          if (_n)  { s5 = _c; i5 = _i; } _r |= _n;\
    _n = !_r && (s6 == thr);          if (_n)  { s6 = _c; i6 = _i; } _r |= _n;\
    _n = !_r && (s7 == thr);          if (_n)  { s7 = _c; i7 = _i; } _r |= _n;\
    _n = !_r;                         if (_n)  { s8 = _c; i8 = _i; }          \
    thr = fminf(fminf(fminf(fminf(s0, s1), fminf(s2, s3)),                    \
                      fminf(fminf(s4, s5), fminf(s6, s7))), s8);              \
} while (0)

#define DRAIN() do {                                                          \
    int _m = __reduce_max_sync(0xffffffffu, cnt);                             \
    for (int _e = 0; _e < _m; ++_e) {                                         \
        if (_e < cnt) {                                                       \
            ull _v = mybuf[_e];                                               \
            float _sc = __uint_as_float((unsigned)_v);                        \
            int _id = (int)(_v >> 32);                                        \
            if (_sc > thr) { INS9(_sc, _id); }                                \
        }                                                                     \
    }                                                                         \
    cnt = 0;                                                                  \
} while (0)

__global__ void __launch_bounds__(256) k_knn() {
    __shared__ __align__(16) char sbuf[45056];
    // phase A: [0,24576) = KT records of 48B; [24576,45056) = lane buffers
    // phase B: msc[32*72] floats (9216B) + mix[32*72] ints (9216B), reuse [0,18432)
    float* msc = (float*)sbuf;
    int*   mix = (int*)(sbuf + 9216);

    int t = threadIdx.x;
    int w = t >> 5;          // slice warp 0..7
    int lane = t & 31;       // query lane
    int qb = blockIdx.x * QB;
    int gq = qb + lane;

    ull* mybuf = (ull*)(sbuf + BUFOFF) + t * BCAP;
    int cnt = 0;

    float4 qa = ((const float4*)g_h2)[gq * 2];
    float4 qc = ((const float4*)g_h2)[gq * 2 + 1];
    float q0 = qa.x, q1 = qa.y, q2 = qa.z, q3 = qa.w;
    float q4 = qc.x, q5 = qc.y, q6 = qc.z, q7 = qc.w;

    float s0 = -INFINITY, s1 = -INFINITY, s2 = -INFINITY, s3 = -INFINITY,
          s4 = -INFINITY, s5 = -INFINITY, s6 = -INFINITY, s7 = -INFINITY,
          s8 = -INFINITY;
    int i0 = 0, i1 = 0, i2 = 0, i3 = 0, i4 = 0, i5 = 0, i6 = 0, i7 = 0, i8 = 0;
    float thr = -INFINITY;

    for (int tb = 0; tb < NN; tb += KT) {
        __syncthreads();
#pragma unroll
        for (int v = t; v < KT; v += 256) {
            float4 a = ((const float4*)g_h2)[(tb + v) * 2];
            float4 b = ((const float4*)g_h2)[(tb + v) * 2 + 1];
            char* rec = sbuf + v * RECB;
            *(float4*)rec        = a;
            *(float4*)(rec + 16) = b;
            float sq = a.x * a.x + a.y * a.y + a.z * a.z + a.w * a.w +
                       b.x * b.x + b.y * b.y + b.z * b.z + b.w * b.w;
            *(float*)(rec + 32) = -0.5f * sq;
        }
        __syncthreads();
        // warp w scans points [w*64, w*64+64): identical address across lanes
        const char* rec = sbuf + (w << 6) * RECB;
#pragma unroll 2
        for (int pp = 0; pp < 64; ++pp) {
            float4 A = *(const float4*)(rec);
            float4 B = *(const float4*)(rec + 16);
            float  n = *(const float*)(rec + 32);
            rec += RECB;
            float acc = fmaf(A.x, q0, fmaf(A.y, q1, fmaf(A.z, q2, fmaf(A.w, q3,
                        fmaf(B.x, q4, fmaf(B.y, q5, fmaf(B.z, q6, fmaf(B.w, q7, n))))))));
            if (acc > thr) {
                int j = tb + (w << 6) + pp;
                mybuf[cnt] = (((ull)(unsigned)j) << 32) | (ull)__float_as_uint(acc);
                ++cnt;
            }
            if (pp & 1) {
                if (__any_sync(0xffffffffu, cnt >= 9)) { DRAIN(); }
            }
        }
    }
    DRAIN();   // flush remaining candidates

    __syncthreads();
    {
        int b = lane * 72 + w * 9;
        msc[b + 0] = s0; msc[b + 1] = s1; msc[b + 2] = s2; msc[b + 3] = s3;
        msc[b + 4] = s4; msc[b + 5] = s5; msc[b + 6] = s6; msc[b + 7] = s7;
        msc[b + 8] = s8;
        mix[b + 0] = i0; mix[b + 1] = i1; mix[b + 2] = i2; mix[b + 3] = i3;
        mix[b + 4] = i4; mix[b + 5] = i5; mix[b + 6] = i6; mix[b + 7] = i7;
        mix[b + 8] = i8;
    }
    __syncthreads();

    if (t < QB) {
        // select top-8 of 72 candidates for query qb+t (score desc, idx asc),
        // skipping self (the global max, present exactly once). No duplicates.
        int q = qb + t;
        int written = 0;
        for (int pick = 0; pick < 9 && written < 8; ++pick) {
            float bs = -INFINITY; int bi = 0x7fffffff; int bp = 0;
            for (int e = 0; e < 72; ++e) {
                float v = msc[t * 72 + e]; int id = mix[t * 72 + e];
                if (v > bs || (v == bs && id < bi)) { bs = v; bi = id; bp = e; }
            }
            msc[t * 72 + bp] = -INFINITY;
            if (bi != q) { g_knn[q * 8 + written] = bi; ++written; }
        }
    }
}

// ---------------- conv3: h2[N,8] -> h3[N,8] over kNN edges (16->8 relu ->8) --
__global__ void k_conv3(const float* __restrict__ w1, const float* __restrict__ b1,
                        const float* __restrict__ w2, const float* __restrict__ b2) {
    __shared__ float sw1[128], sb1[8], sw2[64], sb2[8];
    int t = threadIdx.x;
    for (int v = t; v < 128; v += blockDim.x) sw1[v] = w1[v];
    for (int v = t; v < 64;  v += blockDim.x) sw2[v] = w2[v];
    if (t < 8) { sb1[t] = b1[t]; sb2[t] = b2[t]; }
    __syncthreads();
    int i = blockIdx.x * blockDim.x + t;
    float xi[8];
    {
        float4 a = ((const float4*)g_h2)[i * 2];
        float4 b = ((const float4*)g_h2)[i * 2 + 1];
        xi[0] = a.x; xi[1] = a.y; xi[2] = a.z; xi[3] = a.w;
        xi[4] = b.x; xi[5] = b.y; xi[6] = b.z; xi[7] = b.w;
    }
    float out[8];
#pragma unroll
    for (int o = 0; o < 8; ++o) out[o] = 0.0f;
#pragma unroll
    for (int n = 0; n < 8; ++n) {
        int j = g_knn[i * 8 + n];
        float4 c = ((const float4*)g_h2)[j * 2];
        float4 d = ((const float4*)g_h2)[j * 2 + 1];
        float xj[8] = { c.x, c.y, c.z, c.w, d.x, d.y, d.z, d.w };
        float h[8];
#pragma unroll
        for (int o = 0; o < 8; ++o) h[o] = sb1[o];
#pragma unroll
        for (int f = 0; f < 8; ++f) {
            float m0 = xi[f], m1 = xj[f] - xi[f];
#pragma unroll
            for (int o = 0; o < 8; ++o)
                h[o] += m0 * sw1[f * 8 + o] + m1 * sw1[(8 + f) * 8 + o];
        }
#pragma unroll
        for (int o = 0; o < 8; ++o) h[o] = fmaxf(h[o], 0.0f);
#pragma unroll
        for (int o = 0; o < 8; ++o) {
            float v = sb2[o];
#pragma unroll
            for (int f = 0; f < 8; ++f) v += h[f] * sw2[f * 8 + o];
            out[o] = fmaxf(out[o], v);
        }
    }
#pragma unroll
    for (int o = 0; o < 8; ++o) g_h3[i * 8 + o] = out[o];
}

// ---------------- conv4: h3[N,8] -> h4[N,16] over kNN edges (16->16 relu ->16)
__global__ void k_conv4(const float* __restrict__ w1, const float* __restrict__ b1,
                        const float* __restrict__ w2, const float* __restrict__ b2) {
    __shared__ float sw1[256], sb1[16], sw2[256], sb2[16];
    int t = threadIdx.x;
    for (int v = t; v < 256; v += blockDim.x) { sw1[v] = w1[v]; sw2[v] = w2[v]; }
    if (t < 16) { sb1[t] = b1[t]; sb2[t] = b2[t]; }
    __syncthreads();
    int i = blockIdx.x * blockDim.x + t;
    float xi[8];
    {
        float4 a = ((const float4*)g_h3)[i * 2];
        float4 b = ((const float4*)g_h3)[i * 2 + 1];
        xi[0] = a.x; xi[1] = a.y; xi[2] = a.z; xi[3] = a.w;
        xi[4] = b.x; xi[5] = b.y; xi[6] = b.z; xi[7] = b.w;
    }
    float out[16];
#pragma unroll
    for (int o = 0; o < 16; ++o) out[o] = 0.0f;
#pragma unroll
    for (int n = 0; n < 8; ++n) {
        int j = g_knn[i * 8 + n];
        float4 c = ((const float4*)g_h3)[j * 2];
        float4 d = ((const float4*)g_h3)[j * 2 + 1];
        float xj[8] = { c.x, c.y, c.z, c.w, d.x, d.y, d.z, d.w };
        float h[16];
#pragma unroll
        for (int o = 0; o < 16; ++o) h[o] = sb1[o];
#pragma unroll
        for (int f = 0; f < 8; ++f) {
            float m0 = xi[f], m1 = xj[f] - xi[f];
#pragma unroll
            for (int o = 0; o < 16; ++o)
                h[o] += m0 * sw1[f * 16 + o] + m1 * sw1[(8 + f) * 16 + o];
        }
#pragma unroll
        for (int o = 0; o < 16; ++o) h[o] = fmaxf(h[o], 0.0f);
#pragma unroll
        for (int o = 0; o < 16; ++o) {
            float v = sb2[o];
#pragma unroll
            for (int f = 0; f < 16; ++f) v += h[f] * sw2[f * 16 + o];
            out[o] = fmaxf(out[o], v);
        }
    }
#pragma unroll
    for (int o = 0; o < 16; ++o) g_h4[i * 16 + o] = out[o];
}

// ---------------- global max pool + MLP head + sigmoid -----------------------
__global__ void k_pool(const float* __restrict__ fw, const float* __restrict__ fb,
                       const float* __restrict__ ow, const float* __restrict__ ob,
                       float* __restrict__ out) {
    __shared__ float s[128 * 16];
    int g = blockIdx.x, t = threadIdx.x;
    int node = g * 128 + t;
#pragma unroll
    for (int f = 0; f < 16; ++f) s[t * 16 + f] = g_h4[node * 16 + f];
    __syncthreads();
    for (int st = 64; st > 0; st >>= 1) {
        if (t < st) {
#pragma unroll
            for (int f = 0; f < 16; ++f)
                s[t * 16 + f] = fmaxf(s[t * 16 + f], s[(t + st) * 16 + f]);
        }
        __syncthreads();
    }
    if (t == 0) {
        float z = ob[0];
#pragma unroll
        for (int o = 0; o < 6; ++o) {
            float y = fb[o];
#pragma unroll
            for (int f = 0; f < 16; ++f) y += s[f] * fw[f * 6 + o];
            z += fmaxf(y, 0.0f) * ow[o];
        }
        out[g] = 1.0f / (1.0f + expf(-z));
    }
}

// ---------------- launch ------------------------------------------------------
extern "C" void kernel_launch(void* const* d_in, const int* in_sizes, int n_in,
                              void* d_out, int out_size) {
    const float* x    = (const float*)d_in[0];
    const int*   ei   = (const int*)d_in[1];
    const float* c1w1 = (const float*)d_in[3];
    const float* c1b1 = (const float*)d_in[4];
    const float* c1w2 = (const float*)d_in[5];
    const float* c1b2 = (const float*)d_in[6];
    const float* c2w1 = (const float*)d_in[7];
    const float* c2b1 = (const float*)d_in[8];
    const float* c2w2 = (const float*)d_in[9];
    const float* c2b2 = (const float*)d_in[10];
    const float* c3w1 = (const float*)d_in[11];
    const float* c3b1 = (const float*)d_in[12];
    const float* c3w2 = (const float*)d_in[13];
    const float* c3b2 = (const float*)d_in[14];
    const float* c4w1 = (const float*)d_in[15];
    const float* c4b1 = (const float*)d_in[16];
    const float* c4w2 = (const float*)d_in[17];
    const float* c4b2 = (const float*)d_in[18];
    const float* fc3w = (const float*)d_in[19];
    const float* fc3b = (const float*)d_in[20];
    const float* outw = (const float*)d_in[21];
    const float* outb = (const float*)d_in[22];

    k_init <<< (NN * 16 + 255) / 256, 256 >>> ();
    k_conv1<<< E0C / 256, 256 >>>(x, ei, c1w1, c1b1, c1w2, c1b2);
    k_conv2<<< E0C / 256, 256 >>>(ei, c2w1, c2b1, c2w2, c2b2);
    k_knn  <<< NN / QB, 256 >>>();
    k_conv3<<< NN / 128, 128 >>>(c3w1, c3b1, c3w2, c3b2);
    k_conv4<<< NN / 128, 128 >>>(c4w1, c4b1, c4w2, c4b2);
    k_pool <<< GG, 128 >>>(fc3w, fc3b, outw, outb, (float*)d_out);
}